// round 5
// baseline (speedup 1.0000x reference)
#include <cuda_runtime.h>
#include <math.h>

// B=2, DIM=32, H=W=512, FOLD=8, P=2, HDIM=96, NCLS=16, CV=96
// S=4, tile 64x64, N=4096 px/tile, 128 tiles, 16 sub-blocks of 256 px per tile.
// out: center_feat [2,256,96]=49152 | labels [2,16,256]=8192 | spix_map [2,512,512]=524288

// ---------------- device scratch (inter-kernel) ----------------
__device__ float  d_cen[128][159][4];        // pooled quadrant means [tile][ch][s]
__device__ float4 d_scst[128 * 4096];        // per-pixel static scores
__device__ float  d_numpart[128][16][384];   // iter-0 weighted feat partial sums [ch*4+s]
__device__ float  d_denpart[128][16][4];
__device__ float  d_onumpart[128][16][384];  // iter-1 masked partial sums
__device__ float  d_wdenpart[128][16][4];
__device__ int    d_cnt[128][64];            // label histogram [s*16+cls]

__device__ __forceinline__ float wredsum(float v) {
#pragma unroll
    for (int o = 16; o; o >>= 1) v += __shfl_xor_sync(0xffffffffu, v, o);
    return v;
}
__device__ __forceinline__ float dot4(float4 v, float4 w) {
    return fmaf(v.x, w.x, fmaf(v.y, w.y, fmaf(v.z, w.z, v.w * w.w)));
}

// ================= Kernel 1: pooling =================
// grid = 2*159 (b,ch), block = 512. Warp w owns a 32-row band (f1=w>>1, qy=w&1),
// 16 column-block accumulators -> 16 quadrant sums per warp.
__global__ void __launch_bounds__(512)
pool_kernel(const float* __restrict__ x, const float* __restrict__ feat,
            const float* __restrict__ sdf)
{
    if (blockIdx.x == 0) {  // zero histogram before ITER1 uses it
        for (int i = threadIdx.x; i < 128 * 64; i += 512) ((int*)d_cnt)[i] = 0;
    }
    const int id = blockIdx.x;
    const int b = id / 159, ch = id % 159;
    const float* src;
    if (ch < 32)      src = x    + (((size_t)(b * 32 + ch)) << 18);
    else if (ch < 63) src = sdf  + (((size_t)(b * 31 + (ch - 32))) << 18);
    else              src = feat + (((size_t)(b * 96 + (ch - 63))) << 18);

    const int w = threadIdx.x >> 5, lane = threadIdx.x & 31;
    const int f1 = w >> 1, qy = w & 1;
    const float* rbase = src + (w * 32) * 512 + lane;

    float acc[16];
#pragma unroll
    for (int cb = 0; cb < 16; cb++) acc[cb] = 0.f;
#pragma unroll 2
    for (int r = 0; r < 32; r++) {
        const float* rp = rbase + r * 512;
#pragma unroll
        for (int cb = 0; cb < 16; cb++) acc[cb] += rp[cb * 32];
    }
#pragma unroll
    for (int cb = 0; cb < 16; cb++) {
        float s = wredsum(acc[cb]);
        if (lane == 0) {
            int tile = b * 64 + f1 * 8 + (cb >> 1);
            d_cen[tile][ch][qy * 2 + (cb & 1)] = s * (1.f / 1024.f);
        }
    }
}

// ================= Kernel 2: iter-0 =================
// grid = 2048 (tile*16+sub), block = 256 (1 px/thread over a 4-row block).
__global__ void __launch_bounds__(256)
iter0_kernel(const float* __restrict__ x, const float* __restrict__ feat,
             const float* __restrict__ sdf, const float* __restrict__ Wf,
             const float* __restrict__ bf, const float* __restrict__ Wsdf,
             const float* __restrict__ bsdf)
{
    __shared__ __align__(16) float4 cen4[159];
    __shared__ __align__(16) float4 cdf4[96], csf4[96], g4[32], q4[32];
    __shared__ float Cs[4], n0[4];
    __shared__ __align__(16) float aS[4][256];

    const int tile = blockIdx.x >> 4, sub = blockIdx.x & 15;
    const int tid = threadIdx.x, wid = tid >> 5, lane = tid & 31;
    const int b = tile >> 6, f1 = (tile >> 3) & 7, f2 = tile & 7;
    const int base = f1 * 64 * 512 + f2 * 64;

    for (int i = tid; i < 636; i += 256)
        ((float*)cen4)[i] = ((const float*)d_cen[tile])[i];
    __syncthreads();

    // phase 2a: cdf/csf
    for (int j = tid; j < 384; j += 256) {
        int r = j >> 2, s = j & 3;
        const float* wr = Wf + r * 32;
        float a = bf[r];
#pragma unroll 8
        for (int c = 0; c < 32; c++) a = fmaf(wr[c], ((const float*)&cen4[c])[s], a);
        ((float*)&cdf4[r])[s] = a;
        const float* wr2 = Wsdf + r * 31;
        float a2 = bsdf[r];
#pragma unroll 8
        for (int c = 0; c < 31; c++) a2 = fmaf(wr2[c], ((const float*)&cen4[32 + c])[s], a2);
        ((float*)&csf4[r])[s] = a2;
    }
    __syncthreads();
    // phase 2b: g, q
    if (tid < 128) {
        int c = tid >> 2, s = tid & 3;
        float a = 0.f;
        for (int j = 0; j < 96; j++) a = fmaf(Wf[j * 32 + c], ((const float*)&cdf4[j])[s], a);
        ((float*)&g4[c])[s] = a;
    } else if (tid < 252) {
        int t2 = tid - 128; int c = t2 >> 2, s = t2 & 3;
        float a = 0.f;
        for (int j = 0; j < 96; j++) a = fmaf(Wsdf[j * 31 + c], ((const float*)&csf4[j])[s], a);
        ((float*)&q4[c])[s] = a;
    }
    __syncthreads();
    // phase 2c: Cs, n0
    if (tid < 4) {
        int s = tid;
        float kf = 0.f, ks = 0.f, nd = 0.f, ns = 0.f;
        for (int j = 0; j < 96; j++) {
            float d = ((const float*)&cdf4[j])[s];
            float e = ((const float*)&csf4[j])[s];
            kf = fmaf(bf[j], d, kf); ks = fmaf(bsdf[j], e, ks);
            nd = fmaf(d, d, nd);     ns = fmaf(e, e, ns);
        }
        Cs[s] = 2.f * kf + 2.f * ks - nd - ns;
    } else if (tid < 8) {
        int s = tid - 4;
        float a = 0.f;
        for (int c = 0; c < 96; c++) { float v = ((const float*)&cen4[63 + c])[s]; a = fmaf(v, v, a); }
        n0[s] = a;
    }
    __syncthreads();

    // ---------------- scoring ----------------
    const float* xb = x    + (((size_t)(b * 32)) << 18) + base;
    const float* sb = sdf  + (((size_t)(b * 31)) << 18) + base;
    const float* fb = feat + (((size_t)(b * 96)) << 18) + base;

    const int p   = sub * 256 + tid;
    const int pix = (p >> 6) * 512 + (p & 63);
    float r0 = 0.f, r1 = 0.f, r2 = 0.f, r3 = 0.f;
    {
        const float* xp = xb + pix;
#pragma unroll 8
        for (int c = 0; c < 32; c++) {
            float v = xp[((size_t)c) << 18];
            float4 g = g4[c];
            r0 = fmaf(v, g.x, r0); r1 = fmaf(v, g.y, r1);
            r2 = fmaf(v, g.z, r2); r3 = fmaf(v, g.w, r3);
        }
        const float* sp = sb + pix;
#pragma unroll 8
        for (int c = 0; c < 31; c++) {
            float v = sp[((size_t)c) << 18];
            float4 g = q4[c];
            r0 = fmaf(v, g.x, r0); r1 = fmaf(v, g.y, r1);
            r2 = fmaf(v, g.z, r2); r3 = fmaf(v, g.w, r3);
        }
    }
    float st0 = 2.f * r0 + Cs[0], st1 = 2.f * r1 + Cs[1];
    float st2 = 2.f * r2 + Cs[2], st3 = 2.f * r3 + Cs[3];
    d_scst[tile * 4096 + p] = make_float4(st0, st1, st2, st3);

    float f0 = 0.f, f1_ = 0.f, f2_ = 0.f, f3 = 0.f;
    {
        const float* fp = fb + pix;
#pragma unroll 8
        for (int c = 0; c < 96; c++) {
            float v = fp[((size_t)c) << 18];
            float4 g = cen4[63 + c];
            f0 = fmaf(v, g.x, f0); f1_ = fmaf(v, g.y, f1_);
            f2_ = fmaf(v, g.z, f2_); f3 = fmaf(v, g.w, f3);
        }
    }
    float q0 = st0 + 2.f * f0 - n0[0];
    float q1 = st1 + 2.f * f1_ - n0[1];
    float q2 = st2 + 2.f * f2_ - n0[2];
    float q3 = st3 + 2.f * f3 - n0[3];
    float mx = fmaxf(fmaxf(q0, q1), fmaxf(q2, q3));
    float e0 = expf(q0 - mx), e1 = expf(q1 - mx), e2 = expf(q2 - mx), e3 = expf(q3 - mx);
    float inv = 1.f / (e0 + e1 + e2 + e3);
    aS[0][tid] = e0 * inv;
    aS[1][tid] = e1 * inv;
    aS[2][tid] = e2 * inv;
    aS[3][tid] = e3 * inv;
    __syncthreads();

    // den partials: warps 0..3
    if (wid < 4) {
        float a = 0.f;
#pragma unroll
        for (int k = 0; k < 8; k++) a += aS[wid][lane + 32 * k];
        a = wredsum(a);
        if (lane == 0) d_denpart[tile][sub][wid] = a;
    }

    // accumulation: warp owns 12 channels; rows are L1/L2-hot from scoring
    {
        const float* fbase = fb + (4 * sub) * 512;
        for (int cc = 0; cc < 12; cc++) {
            const int c = wid * 12 + cc;
            const float* cp = fbase + (((size_t)c) << 18);
            float a0 = 0.f, a1 = 0.f, a2 = 0.f, a3 = 0.f;
#pragma unroll
            for (int k = 0; k < 2; k++) {
                int idx = k * 32 + lane;
                int row = idx >> 4, c4 = idx & 15;
                float4 v = *(const float4*)(cp + row * 512 + c4 * 4);
                int px = row * 64 + c4 * 4;
                float4 w0 = *(const float4*)&aS[0][px];
                float4 w1 = *(const float4*)&aS[1][px];
                float4 w2 = *(const float4*)&aS[2][px];
                float4 w3 = *(const float4*)&aS[3][px];
                a0 += dot4(v, w0); a1 += dot4(v, w1);
                a2 += dot4(v, w2); a3 += dot4(v, w3);
            }
            a0 = wredsum(a0); a1 = wredsum(a1); a2 = wredsum(a2); a3 = wredsum(a3);
            if (lane == 0) {
                float* dst = &d_numpart[tile][sub][c * 4];
                dst[0] = a0; dst[1] = a1; dst[2] = a2; dst[3] = a3;
            }
        }
    }
}

// ================= Kernel 3: iter-1 =================
__global__ void __launch_bounds__(256)
iter1_kernel(const float* __restrict__ feat, const int* __restrict__ gt,
             float* __restrict__ out)
{
    __shared__ __align__(16) float4 cpf1[96];
    __shared__ float dens[4], u[4];
    __shared__ __align__(16) float aS[4][256];
    __shared__ int hcnt[64];

    const int tile = blockIdx.x >> 4, sub = blockIdx.x & 15;
    const int tid = threadIdx.x, wid = tid >> 5, lane = tid & 31;
    const int b = tile >> 6, f1 = (tile >> 3) & 7, f2 = tile & 7;
    const int base = f1 * 64 * 512 + f2 * 64;

    if (tid < 4) {
        float a = 0.f;
#pragma unroll
        for (int s2 = 0; s2 < 16; s2++) a += d_denpart[tile][s2][tid];
        dens[tid] = a + 1e-16f;
    }
    if (tid < 64) hcnt[tid] = 0;
    __syncthreads();
    for (int j = tid; j < 384; j += 256) {
        float a = 0.f;
#pragma unroll
        for (int s2 = 0; s2 < 16; s2++) a += d_numpart[tile][s2][j];
        ((float*)cpf1)[j] = a / dens[j & 3];
    }
    __syncthreads();
    if (wid < 4) {
        float a = 0.f;
        for (int c = lane; c < 96; c += 32) {
            float v = ((const float*)&cpf1[c])[wid];
            a = fmaf(v, v, a);
        }
        a = wredsum(a);
        if (lane == 0) u[wid] = a;
    }
    __syncthreads();

    const float* fb = feat + (((size_t)(b * 96)) << 18) + base;
    const int tloc4 = (f1 * 8 + f2) * 4;
    const int* gtb = gt + (size_t)b * 262144 + base;
    float* spix = out + 57344 + (size_t)b * 262144 + base;

    const int p   = sub * 256 + tid;
    const int pix = (p >> 6) * 512 + (p & 63);
    float4 st = d_scst[tile * 4096 + p];
    float f0 = 0.f, f1_ = 0.f, f2_ = 0.f, f3 = 0.f;
    {
        const float* fp = fb + pix;
#pragma unroll 8
        for (int c = 0; c < 96; c++) {
            float v = fp[((size_t)c) << 18];
            float4 g = cpf1[c];
            f0 = fmaf(v, g.x, f0); f1_ = fmaf(v, g.y, f1_);
            f2_ = fmaf(v, g.z, f2_); f3 = fmaf(v, g.w, f3);
        }
    }
    float q0 = st.x + 2.f * f0 - u[0];
    float q1 = st.y + 2.f * f1_ - u[1];
    float q2 = st.z + 2.f * f2_ - u[2];
    float q3 = st.w + 2.f * f3 - u[3];
    int ss = 0; float best = q0;                 // first-max tie rule
    if (q1 > best) { best = q1; ss = 1; }
    if (q2 > best) { best = q2; ss = 2; }
    if (q3 > best) { best = q3; ss = 3; }
    float w = 1.f / (expf(q0 - best) + expf(q1 - best) + expf(q2 - best) + expf(q3 - best));
    aS[0][tid] = (ss == 0) ? w : 0.f;
    aS[1][tid] = (ss == 1) ? w : 0.f;
    aS[2][tid] = (ss == 2) ? w : 0.f;
    aS[3][tid] = (ss == 3) ? w : 0.f;
    atomicAdd(&hcnt[ss * 16 + gtb[pix]], 1);
    spix[pix] = (float)(tloc4 + ss);
    __syncthreads();

    if (wid < 4) {
        float a = 0.f;
#pragma unroll
        for (int k = 0; k < 8; k++) a += aS[wid][lane + 32 * k];
        a = wredsum(a);
        if (lane == 0) d_wdenpart[tile][sub][wid] = a;
    }
    if (tid < 64 && hcnt[tid]) atomicAdd(&d_cnt[tile][tid], hcnt[tid]);

    {
        const float* fbase = fb + (4 * sub) * 512;
        for (int cc = 0; cc < 12; cc++) {
            const int c = wid * 12 + cc;
            const float* cp = fbase + (((size_t)c) << 18);
            float a0 = 0.f, a1 = 0.f, a2 = 0.f, a3 = 0.f;
#pragma unroll
            for (int k = 0; k < 2; k++) {
                int idx = k * 32 + lane;
                int row = idx >> 4, c4 = idx & 15;
                float4 v = *(const float4*)(cp + row * 512 + c4 * 4);
                int px = row * 64 + c4 * 4;
                float4 w0 = *(const float4*)&aS[0][px];
                float4 w1 = *(const float4*)&aS[1][px];
                float4 w2 = *(const float4*)&aS[2][px];
                float4 w3 = *(const float4*)&aS[3][px];
                a0 += dot4(v, w0); a1 += dot4(v, w1);
                a2 += dot4(v, w2); a3 += dot4(v, w3);
            }
            a0 = wredsum(a0); a1 = wredsum(a1); a2 = wredsum(a2); a3 = wredsum(a3);
            if (lane == 0) {
                float* dst = &d_onumpart[tile][sub][c * 4];
                dst[0] = a0; dst[1] = a1; dst[2] = a2; dst[3] = a3;
            }
        }
    }
}

// ================= Kernel 4: final outputs =================
__global__ void __launch_bounds__(384)
final_kernel(float* __restrict__ out)
{
    const int tile = blockIdx.x, tid = threadIdx.x;
    const int b = tile >> 6;
    const int tloc4 = (tile & 63) * 4;
    __shared__ float wden[4];
    if (tid < 4) {
        float a = 0.f;
#pragma unroll
        for (int s2 = 0; s2 < 16; s2++) a += d_wdenpart[tile][s2][tid];
        wden[tid] = a + 1.f;
    }
    __syncthreads();
    {
        int c = tid >> 2, s = tid & 3;
        float a = 0.f;
#pragma unroll
        for (int s2 = 0; s2 < 16; s2++) a += d_onumpart[tile][s2][tid];
        float vc = d_cen[tile][63 + c][s];
        out[(size_t)b * 24576 + (size_t)(tloc4 + s) * 96 + c] = (a + vc) / wden[s];
    }
    if (tid < 64) {
        int s = tid >> 4, cls = tid & 15;
        out[49152 + (size_t)b * 4096 + (size_t)cls * 256 + tloc4 + s] = (float)d_cnt[tile][tid];
    }
}

extern "C" void kernel_launch(void* const* d_in, const int* in_sizes, int n_in,
                              void* d_out, int out_size) {
    const float* x    = (const float*)d_in[0];
    const float* feat = (const float*)d_in[1];
    const float* sdf  = (const float*)d_in[2];
    const float* Wf   = (const float*)d_in[3];
    const float* bf   = (const float*)d_in[4];
    const float* Wsdf = (const float*)d_in[5];
    const float* bsdf = (const float*)d_in[6];
    const int*   gt   = (const int*)d_in[7];
    float* out = (float*)d_out;

    pool_kernel<<<318, 512>>>(x, feat, sdf);
    iter0_kernel<<<2048, 256>>>(x, feat, sdf, Wf, bf, Wsdf, bsdf);
    iter1_kernel<<<2048, 256>>>(feat, gt, out);
    final_kernel<<<128, 384>>>(out);
}